// round 10
// baseline (speedup 1.0000x reference)
#include <cuda_runtime.h>
#include <cuda_fp16.h>
#include <stdint.h>
#include <stddef.h>

#define N_ROWS 8192
#define N_COLS 8192
#define DD     1024

#define NSM      148
#define KCHUNK   256
#define NCHUNKS  (N_COLS / KCHUNK)          // 32
#define NMBAND   (N_ROWS / 128)             // 64
#define NUNITS   (NCHUNKS * NMBAND)         // 2048

// Scratch (no cudaMalloc allowed)
static __device__ __half   g_E[(size_t)N_ROWS * N_COLS];      // weights exp(2m)*2^-4
static __device__ float    g_Spart[(size_t)N_ROWS * NCHUNKS]; // per-(row,kchunk) partial sums
static __device__ __half   g_Xh[(size_t)N_ROWS * DD];         // x fp16 [k][n]
static __device__ unsigned g_flag[NUNITS];                    // unit-ready flags

// ===========================================================================
// Threefry-2x32 (20 rounds), key = (0, 42); JAX partitionable combine o0^o1
// ===========================================================================
__device__ __forceinline__ uint32_t rotl32(uint32_t x, int d) {
    return __funnelshift_l(x, x, d);
}

__device__ __forceinline__ uint32_t threefry_bits(uint32_t t) {
    uint32_t x0 = 0u, x1 = t;
    const uint32_t ks1 = 42u, ks2 = 0x1BD11BF0u;
    x1 += ks1;
#define TF_R(r) { x0 += x1; x1 = rotl32(x1, (r)); x1 ^= x0; }
    TF_R(13) TF_R(15) TF_R(26) TF_R(6)
    x0 += ks1; x1 += ks2 + 1u;
    TF_R(17) TF_R(29) TF_R(16) TF_R(24)
    x0 += ks2; x1 += 2u;
    TF_R(13) TF_R(15) TF_R(26) TF_R(6)
    x1 += ks1 + 3u;
    TF_R(17) TF_R(29) TF_R(16) TF_R(24)
    x0 += ks1; x1 += ks2 + 4u;
    TF_R(13) TF_R(15) TF_R(26) TF_R(6)
    x0 += ks2; x1 += 5u;
#undef TF_R
    return x0 ^ x1;
}

// weight = exp(2*sqrt(2)*erfinv_xla(u)) * 2^-4 ; erfinv matches XLA's Giles poly
__device__ __forceinline__ float gibbs_weight(uint32_t bits) {
    float f = __uint_as_float((bits >> 9) | 0x3f800000u) - 1.0f;
    float u = f * 2.0f + -0.99999994f;
    u = fmaxf(u, -0.99999994f);

    float y = 1.0f - u * u;
    float l; asm("lg2.approx.ftz.f32 %0, %1;" : "=f"(l) : "f"(y));
    float w = l * -0.6931471805599453f;        // -log(1 - u^2)
    float p;
    if (w < 5.0f) {
        w -= 2.5f;
        p = 2.81022636e-08f;
        p = fmaf(p, w, 3.43273939e-07f);
        p = fmaf(p, w, -3.5233877e-06f);
        p = fmaf(p, w, -4.39150654e-06f);
        p = fmaf(p, w, 0.00021858087f);
        p = fmaf(p, w, -0.00125372503f);
        p = fmaf(p, w, -0.00417768164f);
        p = fmaf(p, w, 0.246640727f);
        p = fmaf(p, w, 1.50140941f);
    } else {
        w = sqrtf(w) - 3.0f;
        p = -0.000200214257f;
        p = fmaf(p, w, 0.000100950558f);
        p = fmaf(p, w, 0.00134934322f);
        p = fmaf(p, w, -0.00367342844f);
        p = fmaf(p, w, 0.00573950773f);
        p = fmaf(p, w, -0.0076224613f);
        p = fmaf(p, w, 0.00943887047f);
        p = fmaf(p, w, 1.00167406f);
        p = fmaf(p, w, 2.83297682f);
    }
    float t = p * u;                            // erfinv_xla(u)
    float a = fmaf(t, 4.0805578f, -4.0f);       // 2^(t*2*sqrt2/ln2 - 4)
    float e; asm("ex2.approx.ftz.f32 %0, %1;" : "=f"(e) : "f"(a));
    return e;
}

// ===========================================================================
// Pass 0: x f32 -> fp16 (vectorized) + zero the unit flags
// ===========================================================================
__global__ void convert_x_kernel(const float4* __restrict__ x) {
    int idx = blockIdx.x * 256 + threadIdx.x;   // 0..2097151
    if (idx < NUNITS) g_flag[idx] = 0u;
    float4 v = x[idx];
    __half2 h0 = __floats2half2_rn(v.x, v.y);
    __half2 h1 = __floats2half2_rn(v.z, v.w);
    *(uint2*)(g_Xh + (size_t)idx * 4) = make_uint2(*(uint32_t*)&h0, *(uint32_t*)&h1);
}

// ===========================================================================
// Fused pass: CTAs 0..147 generate E (producer), 148..295 GEMM (consumer).
// Producer unit u = kc*64 + m : rows [m*128, +128), cols [kc*256, +256).
// Consumer: persistent over 512 tiles (8 n-bands x 64 m-bands), BM=BN=128,
// BK=32, warp tile 32x64, 2-stage cp.async (proven R6 datapath) with
// acquire-spin on chunk flags; epilogue sums 32 deterministic partials.
// ===========================================================================
#define BM 128
#define BN 128
#define BK 32
#define SA_LD 40
#define SB_LD 136
#define NTILES (NMBAND * (DD / BN))   // 512

__device__ __forceinline__ void cp_async16(void* smem, const void* gmem) {
    uint32_t s = (uint32_t)__cvta_generic_to_shared(smem);
    asm volatile("cp.async.cg.shared.global [%0], [%1], 16;\n" :: "r"(s), "l"(gmem));
}

__device__ __forceinline__ void wait_flag(int u) {
    unsigned v;
    for (;;) {
        asm volatile("ld.acquire.gpu.global.u32 %0, [%1];"
                     : "=r"(v) : "l"(g_flag + u) : "memory");
        if (v) break;
        __nanosleep(128);
    }
}

__global__ __launch_bounds__(256, 2)
void fused_kernel(float* __restrict__ out) {
    __shared__ __half sA[2][BM][SA_LD];
    __shared__ __half sB[2][BK][SB_LD];

    const int bid  = blockIdx.x;
    const int tid  = threadIdx.x;
    const int wid  = tid >> 5;
    const int lane = tid & 31;

    if (bid < NSM) {
        // ---------------- producer: generate E units ----------------
        for (int u = bid; u < NUNITS; u += NSM) {
            const int kc = u >> 6, m = u & 63;
            const int colbase = kc * KCHUNK + lane * 2;
#pragma unroll 1
            for (int rr = 0; rr < 16; rr++) {
                const int row = m * 128 + wid * 16 + rr;
                const uint32_t base = (uint32_t)row * (uint32_t)N_COLS;
                float part = 0.0f;
#pragma unroll
                for (int j = 0; j < 4; j++) {
                    uint32_t t = base + (uint32_t)(colbase + j * 64);
                    float e0 = gibbs_weight(threefry_bits(t));
                    float e1 = gibbs_weight(threefry_bits(t + 1u));
                    part += e0 + e1;
                    *(__half2*)(g_E + (size_t)base + colbase + j * 64) =
                        __floats2half2_rn(e0, e1);
                }
#pragma unroll
                for (int o = 16; o > 0; o >>= 1)
                    part += __shfl_xor_sync(0xffffffffu, part, o);
                if (lane == 0) g_Spart[row * NCHUNKS + kc] = part;
            }
            __syncthreads();
            if (tid == 0) {
                __threadfence();
                asm volatile("st.release.gpu.global.u32 [%0], %1;"
                             :: "l"(g_flag + u), "r"(1u) : "memory");
            }
        }
        return;
    }

    // ---------------- consumer: persistent GEMM ----------------
    const int wm = wid & 3;    // 4 warp-rows  -> 32 rows each
    const int wn = wid >> 2;   // 2 warp-cols  -> 64 cols each
    const int aR = tid >> 2, aC = (tid & 3) * 8;
    const int bR = tid >> 4, bC = (tid & 15) * 8;

    for (int tile = bid - NSM; tile < NTILES; tile += NSM) {
        const int mb  = tile & 63;
        const int bm0 = mb * BM;
        const int bn0 = (tile >> 6) * BN;

        float acc[2][8][4];
#pragma unroll
        for (int a = 0; a < 2; a++)
#pragma unroll
            for (int b = 0; b < 8; b++)
#pragma unroll
                for (int c = 0; c < 4; c++) acc[a][b][c] = 0.0f;

#define LOAD_TILES(st, k0)                                                                  \
    {                                                                                       \
        cp_async16(&sA[st][aR][aC],      g_E + (size_t)(bm0 + aR) * N_COLS + (k0) + aC);    \
        cp_async16(&sA[st][aR + 64][aC], g_E + (size_t)(bm0 + aR + 64) * N_COLS + (k0) + aC); \
        cp_async16(&sB[st][bR][bC],      g_Xh + (size_t)((k0) + bR) * DD + bn0 + bC);       \
        cp_async16(&sB[st][bR + 16][bC], g_Xh + (size_t)((k0) + bR + 16) * DD + bn0 + bC);  \
        asm volatile("cp.async.commit_group;\n");                                           \
    }

        if (tid == 0) wait_flag(mb);          // chunk 0 of this m-band
        __syncthreads();
        LOAD_TILES(0, 0)

        const int KT = N_COLS / BK;  // 256
        for (int kt = 0; kt < KT; kt++) {
            const int st = kt & 1;
            if (kt + 1 < KT) {
                const int k0 = (kt + 1) * BK;
                if ((k0 & (KCHUNK - 1)) == 0) {        // entering a new 256-k chunk
                    if (tid == 0) wait_flag((k0 >> 8) * 64 + mb);
                    __syncthreads();
                }
                LOAD_TILES(st ^ 1, k0)
                asm volatile("cp.async.wait_group 1;\n");
            } else {
                asm volatile("cp.async.wait_group 0;\n");
            }
            __syncthreads();

#pragma unroll
            for (int kk = 0; kk < 2; kk++) {
                uint32_t a[2][4];
#pragma unroll
                for (int mt = 0; mt < 2; mt++) {
                    uint32_t ad = (uint32_t)__cvta_generic_to_shared(
                        &sA[st][wm * 32 + mt * 16 + (lane & 15)][kk * 16 + (lane >> 4) * 8]);
                    asm volatile(
                        "ldmatrix.sync.aligned.m8n8.x4.shared.b16 {%0,%1,%2,%3}, [%4];"
                        : "=r"(a[mt][0]), "=r"(a[mt][1]), "=r"(a[mt][2]), "=r"(a[mt][3])
                        : "r"(ad));
                }
#pragma unroll
                for (int nt = 0; nt < 4; nt++) {
                    uint32_t b0, b1, b2, b3;
                    uint32_t bd = (uint32_t)__cvta_generic_to_shared(
                        &sB[st][kk * 16 + (lane & 15)][wn * 64 + nt * 16 + (lane >> 4) * 8]);
                    asm volatile(
                        "ldmatrix.sync.aligned.m8n8.x4.trans.shared.b16 {%0,%1,%2,%3}, [%4];"
                        : "=r"(b0), "=r"(b1), "=r"(b2), "=r"(b3)
                        : "r"(bd));
#pragma unroll
                    for (int mt = 0; mt < 2; mt++) {
                        asm volatile(
                            "mma.sync.aligned.m16n8k16.row.col.f32.f16.f16.f32 "
                            "{%0,%1,%2,%3}, {%4,%5,%6,%7}, {%8,%9}, {%0,%1,%2,%3};"
                            : "+f"(acc[mt][2 * nt][0]), "+f"(acc[mt][2 * nt][1]),
                              "+f"(acc[mt][2 * nt][2]), "+f"(acc[mt][2 * nt][3])
                            : "r"(a[mt][0]), "r"(a[mt][1]), "r"(a[mt][2]), "r"(a[mt][3]),
                              "r"(b0), "r"(b1));
                        asm volatile(
                            "mma.sync.aligned.m16n8k16.row.col.f32.f16.f16.f32 "
                            "{%0,%1,%2,%3}, {%4,%5,%6,%7}, {%8,%9}, {%0,%1,%2,%3};"
                            : "+f"(acc[mt][2 * nt + 1][0]), "+f"(acc[mt][2 * nt + 1][1]),
                              "+f"(acc[mt][2 * nt + 1][2]), "+f"(acc[mt][2 * nt + 1][3])
                            : "r"(a[mt][0]), "r"(a[mt][1]), "r"(a[mt][2]), "r"(a[mt][3]),
                              "r"(b2), "r"(b3));
                    }
                }
            }
            __syncthreads();
        }
#undef LOAD_TILES

        // epilogue: S[row] = sum of 32 deterministic chunk partials
#pragma unroll
        for (int mt = 0; mt < 2; mt++) {
            const int r0 = bm0 + wm * 32 + mt * 16 + (lane >> 2);
            float s0 = 0.0f, s1 = 0.0f;
#pragma unroll
            for (int kc = 0; kc < NCHUNKS; kc++) {
                s0 += g_Spart[r0 * NCHUNKS + kc];
                s1 += g_Spart[(r0 + 8) * NCHUNKS + kc];
            }
            const float sc0 = 1.0f / s0;
            const float sc1 = 1.0f / s1;
#pragma unroll
            for (int q = 0; q < 8; q++) {
                const int c0 = bn0 + wn * 64 + q * 8 + (lane & 3) * 2;
                float2 v0 = make_float2(acc[mt][q][0] * sc0, acc[mt][q][1] * sc0);
                float2 v1 = make_float2(acc[mt][q][2] * sc1, acc[mt][q][3] * sc1);
                *(float2*)(out + (size_t)r0 * DD + c0)       = v0;
                *(float2*)(out + (size_t)(r0 + 8) * DD + c0) = v1;
            }
        }
        __syncthreads();   // smem safe for next tile
    }
}

// ---------------------------------------------------------------------------
extern "C" void kernel_launch(void* const* d_in, const int* in_sizes, int n_in,
                              void* d_out, int out_size) {
    (void)in_sizes; (void)n_in; (void)out_size;
    const float* x = (const float*)d_in[0];   // [8192, 1024] f32
    // d_in[1] = edge_index: unused by the reference, unused here.
    float* out = (float*)d_out;               // [8192, 1024] f32

    convert_x_kernel<<<(N_ROWS * DD / 4) / 256, 256>>>((const float4*)x);
    fused_kernel<<<2 * NSM, 256>>>(out);
}

// round 12
// speedup vs baseline: 1.0726x; 1.0726x over previous
#include <cuda_runtime.h>
#include <cuda_fp16.h>
#include <stdint.h>
#include <stddef.h>

#define N_ROWS 8192
#define N_COLS 8192
#define DD     1024

#define NSM    148
#define KCHUNK 256
#define NKC    (N_COLS / KCHUNK)       // 32 k-chunks
#define NMB    (N_ROWS / 64)           // 128 m-bands (64 rows)
#define NUNITS (NMB * NKC)             // 4096, u = mb*32 + kc  (m-major!)
#define NTILES (NMB * (DD / 128))      // 1024, tile = mb*8 + nb

// Scratch (no cudaMalloc allowed)
static __device__ __half   g_E[(size_t)N_ROWS * N_COLS];    // exp(2m)*2^-4
static __device__ float    g_Spart[(size_t)N_ROWS * NKC];   // per-(row,kchunk) partials
static __device__ __half   g_Xh[(size_t)N_ROWS * DD];       // x fp16 [k][n]
static __device__ unsigned g_flag[NUNITS];                  // unit-ready flags

// ===========================================================================
// Threefry-2x32 (20 rounds), key = (0, 42); JAX partitionable combine o0^o1
// ===========================================================================
__device__ __forceinline__ uint32_t rotl32(uint32_t x, int d) {
    return __funnelshift_l(x, x, d);
}

__device__ __forceinline__ uint32_t threefry_bits(uint32_t t) {
    uint32_t x0 = 0u, x1 = t;
    const uint32_t ks1 = 42u, ks2 = 0x1BD11BF0u;
    x1 += ks1;
#define TF_R(r) { x0 += x1; x1 = rotl32(x1, (r)); x1 ^= x0; }
    TF_R(13) TF_R(15) TF_R(26) TF_R(6)
    x0 += ks1; x1 += ks2 + 1u;
    TF_R(17) TF_R(29) TF_R(16) TF_R(24)
    x0 += ks2; x1 += 2u;
    TF_R(13) TF_R(15) TF_R(26) TF_R(6)
    x1 += ks1 + 3u;
    TF_R(17) TF_R(29) TF_R(16) TF_R(24)
    x0 += ks1; x1 += ks2 + 4u;
    TF_R(13) TF_R(15) TF_R(26) TF_R(6)
    x0 += ks2; x1 += 5u;
#undef TF_R
    return x0 ^ x1;
}

// weight = exp(2*sqrt(2)*erfinv_xla(u)) * 2^-4 ; matches XLA's Giles poly
__device__ __forceinline__ float gibbs_weight(uint32_t bits) {
    float f = __uint_as_float((bits >> 9) | 0x3f800000u) - 1.0f;
    float u = f * 2.0f + -0.99999994f;
    u = fmaxf(u, -0.99999994f);

    float y = 1.0f - u * u;
    float l; asm("lg2.approx.ftz.f32 %0, %1;" : "=f"(l) : "f"(y));
    float w = l * -0.6931471805599453f;
    float p;
    if (w < 5.0f) {
        w -= 2.5f;
        p = 2.81022636e-08f;
        p = fmaf(p, w, 3.43273939e-07f);
        p = fmaf(p, w, -3.5233877e-06f);
        p = fmaf(p, w, -4.39150654e-06f);
        p = fmaf(p, w, 0.00021858087f);
        p = fmaf(p, w, -0.00125372503f);
        p = fmaf(p, w, -0.00417768164f);
        p = fmaf(p, w, 0.246640727f);
        p = fmaf(p, w, 1.50140941f);
    } else {
        w = sqrtf(w) - 3.0f;
        p = -0.000200214257f;
        p = fmaf(p, w, 0.000100950558f);
        p = fmaf(p, w, 0.00134934322f);
        p = fmaf(p, w, -0.00367342844f);
        p = fmaf(p, w, 0.00573950773f);
        p = fmaf(p, w, -0.0076224613f);
        p = fmaf(p, w, 0.00943887047f);
        p = fmaf(p, w, 1.00167406f);
        p = fmaf(p, w, 2.83297682f);
    }
    float t = p * u;
    float a = fmaf(t, 4.0805578f, -4.0f);       // 2^(t*2*sqrt2/ln2 - 4)
    float e; asm("ex2.approx.ftz.f32 %0, %1;" : "=f"(e) : "f"(a));
    return e;
}

// ===========================================================================
// Pass 0: x f32 -> fp16 + zero flags
// ===========================================================================
__global__ void convert_x_kernel(const float4* __restrict__ x) {
    int idx = blockIdx.x * 256 + threadIdx.x;
    if (idx < NUNITS) g_flag[idx] = 0u;
    float4 v = x[idx];
    __half2 h0 = __floats2half2_rn(v.x, v.y);
    __half2 h1 = __floats2half2_rn(v.z, v.w);
    *(uint2*)(g_Xh + (size_t)idx * 4) = make_uint2(*(uint32_t*)&h0, *(uint32_t*)&h1);
}

// ===========================================================================
// Fused: 148 CTAs x 512 thr. Warps 0-7 consumer GEMM, warps 8-15 producer gen.
// ===========================================================================
#define BM 64
#define BN 128
#define BK 32
#define SA_LD 40
#define SB_LD 136

__device__ __forceinline__ void cp_async16(void* smem, const void* gmem) {
    uint32_t s = (uint32_t)__cvta_generic_to_shared(smem);
    asm volatile("cp.async.cg.shared.global [%0], [%1], 16;\n" :: "r"(s), "l"(gmem));
}

__device__ __forceinline__ void wait_flag(int u) {
    unsigned v;
    for (;;) {
        asm volatile("ld.acquire.gpu.global.u32 %0, [%1];"
                     : "=r"(v) : "l"(g_flag + u) : "memory");
        if (v) break;
        __nanosleep(64);
    }
}

#define BAR_C() asm volatile("bar.sync 1, 256;" ::: "memory")   // consumer warps
#define BAR_P() asm volatile("bar.sync 2, 256;" ::: "memory")   // producer warps

__global__ __launch_bounds__(512, 1)
void fused_kernel(float* __restrict__ out) {
    __shared__ __half sA[2][BM][SA_LD];
    __shared__ __half sB[2][BK][SB_LD];
    __shared__ float  srow[BM];

    const int bid  = blockIdx.x;
    const int tid  = threadIdx.x;
    const int wid  = tid >> 5;
    const int lane = tid & 31;

    if (wid >= 8) {
        // ================= producer: warps 8..15 =================
        const int pw = wid - 8;
        for (int u = bid; u < NUNITS; u += NSM) {
            const int mb = u >> 5, kc = u & 31;
#pragma unroll 1
            for (int rr = 0; rr < 8; rr++) {
                const int row = mb * 64 + pw * 8 + rr;
                const uint32_t base = (uint32_t)row * (uint32_t)N_COLS
                                    + (uint32_t)(kc * KCHUNK);
                float part = 0.0f;
#pragma unroll
                for (int j = 0; j < 4; j++) {
                    uint32_t c = (uint32_t)(lane * 2 + j * 64);
                    uint32_t t = base + c;
                    float e0 = gibbs_weight(threefry_bits(t));
                    float e1 = gibbs_weight(threefry_bits(t + 1u));
                    part += e0 + e1;
                    *(__half2*)(g_E + (size_t)base + c) = __floats2half2_rn(e0, e1);
                }
#pragma unroll
                for (int o = 16; o > 0; o >>= 1)
                    part += __shfl_xor_sync(0xffffffffu, part, o);
                if (lane == 0) g_Spart[row * NKC + kc] = part;
            }
            BAR_P();
            if (tid == 256) {
                __threadfence();
                asm volatile("st.release.gpu.global.u32 [%0], %1;"
                             :: "l"(g_flag + u), "r"(1u) : "memory");
            }
        }
        return;
    }

    // ================= consumer: warps 0..7 =================
    const int ct = tid;            // 0..255
    const int wm = wid & 1;        // 2 warp-rows of 32
    const int wn = wid >> 1;       // 4 warp-cols of 32
    const int aR = ct >> 2, aC = (ct & 3) * 8;
    const int bR = ct >> 4, bC = (ct & 15) * 8;

    for (int tile = bid; tile < NTILES; tile += NSM) {
        const int mb  = tile >> 3;
        const int bm0 = mb * BM;
        const int bn0 = (tile & 7) * BN;

        float acc[2][4][4];
#pragma unroll
        for (int a = 0; a < 2; a++)
#pragma unroll
            for (int b = 0; b < 4; b++)
#pragma unroll
                for (int c = 0; c < 4; c++) acc[a][b][c] = 0.0f;

#define LOAD_TILES(st, k0)                                                               \
    {                                                                                    \
        cp_async16(&sA[st][aR][aC],     g_E + (size_t)(bm0 + aR) * N_COLS + (k0) + aC);  \
        cp_async16(&sB[st][bR][bC],      g_Xh + (size_t)((k0) + bR) * DD + bn0 + bC);    \
        cp_async16(&sB[st][bR + 16][bC], g_Xh + (size_t)((k0) + bR + 16) * DD + bn0 + bC); \
        asm volatile("cp.async.commit_group;\n");                                        \
    }

        if (ct == 0) wait_flag(mb * NKC);
        BAR_C();
        LOAD_TILES(0, 0)

        const int KT = N_COLS / BK;  // 256
        for (int kt = 0; kt < KT; kt++) {
            const int st = kt & 1;
            if (kt + 1 < KT) {
                const int k0 = (kt + 1) * BK;
                if ((k0 & (KCHUNK - 1)) == 0) {
                    if (ct == 0) wait_flag(mb * NKC + (k0 >> 8));
                    BAR_C();
                }
                LOAD_TILES(st ^ 1, k0)
                asm volatile("cp.async.wait_group 1;\n");
            } else {
                asm volatile("cp.async.wait_group 0;\n");
            }
            BAR_C();

#pragma unroll
            for (int kk = 0; kk < 2; kk++) {
                uint32_t a[2][4];
#pragma unroll
                for (int mt = 0; mt < 2; mt++) {
                    uint32_t ad = (uint32_t)__cvta_generic_to_shared(
                        &sA[st][wm * 32 + mt * 16 + (lane & 15)][kk * 16 + (lane >> 4) * 8]);
                    asm volatile(
                        "ldmatrix.sync.aligned.m8n8.x4.shared.b16 {%0,%1,%2,%3}, [%4];"
                        : "=r"(a[mt][0]), "=r"(a[mt][1]), "=r"(a[mt][2]), "=r"(a[mt][3])
                        : "r"(ad));
                }
#pragma unroll
                for (int nt = 0; nt < 2; nt++) {
                    uint32_t b0, b1, b2, b3;
                    uint32_t bd = (uint32_t)__cvta_generic_to_shared(
                        &sB[st][kk * 16 + (lane & 15)][wn * 32 + nt * 16 + (lane >> 4) * 8]);
                    asm volatile(
                        "ldmatrix.sync.aligned.m8n8.x4.trans.shared.b16 {%0,%1,%2,%3}, [%4];"
                        : "=r"(b0), "=r"(b1), "=r"(b2), "=r"(b3)
                        : "r"(bd));
#pragma unroll
                    for (int mt = 0; mt < 2; mt++) {
                        asm volatile(
                            "mma.sync.aligned.m16n8k16.row.col.f32.f16.f16.f32 "
                            "{%0,%1,%2,%3}, {%4,%5,%6,%7}, {%8,%9}, {%0,%1,%2,%3};"
                            : "+f"(acc[mt][2 * nt][0]), "+f"(acc[mt][2 * nt][1]),
                              "+f"(acc[mt][2 * nt][2]), "+f"(acc[mt][2 * nt][3])
                            : "r"(a[mt][0]), "r"(a[mt][1]), "r"(a[mt][2]), "r"(a[mt][3]),
                              "r"(b0), "r"(b1));
                        asm volatile(
                            "mma.sync.aligned.m16n8k16.row.col.f32.f16.f16.f32 "
                            "{%0,%1,%2,%3}, {%4,%5,%6,%7}, {%8,%9}, {%0,%1,%2,%3};"
                            : "+f"(acc[mt][2 * nt + 1][0]), "+f"(acc[mt][2 * nt + 1][1]),
                              "+f"(acc[mt][2 * nt + 1][2]), "+f"(acc[mt][2 * nt + 1][3])
                            : "r"(a[mt][0]), "r"(a[mt][1]), "r"(a[mt][2]), "r"(a[mt][3]),
                              "r"(b2), "r"(b3));
                    }
                }
            }
            BAR_C();
        }
#undef LOAD_TILES

        // row scales: deterministic sum of 32 chunk partials (all flags acquired)
        {
            const int row = ct >> 2;
            float s = 0.0f;
#pragma unroll
            for (int k = 0; k < 8; k++)
                s += g_Spart[(bm0 + row) * NKC + (ct & 3) * 8 + k];
            s += __shfl_xor_sync(0xffffffffu, s, 1);
            s += __shfl_xor_sync(0xffffffffu, s, 2);
            if ((lane & 3) == 0) srow[row] = s;
        }
        BAR_C();

#pragma unroll
        for (int mt = 0; mt < 2; mt++) {
            const int lr = wm * 32 + mt * 16 + (lane >> 2);
            const int r0 = bm0 + lr;
            const float sc0 = 1.0f / srow[lr];
            const float sc1 = 1.0f / srow[lr + 8];
#pragma unroll
            for (int nt = 0; nt < 2; nt++)
#pragma unroll
                for (int h = 0; h < 2; h++) {
                    const int q  = nt * 2 + h;
                    const int c0 = bn0 + wn * 32 + nt * 16 + h * 8 + (lane & 3) * 2;
                    float2 v0 = make_float2(acc[mt][q][0] * sc0, acc[mt][q][1] * sc0);
                    float2 v1 = make_float2(acc[mt][q][2] * sc1, acc[mt][q][3] * sc1);
                    *(float2*)(out + (size_t)r0 * DD + c0)       = v0;
                    *(float2*)(out + (size_t)(r0 + 8) * DD + c0) = v1;
                }
        }
        BAR_C();
    }
}

// ---------------------------------------------------------------------------
extern "C" void kernel_launch(void* const* d_in, const int* in_sizes, int n_in,
                              void* d_out, int out_size) {
    (void)in_sizes; (void)n_in; (void)out_size;
    const float* x = (const float*)d_in[0];   // [8192, 1024] f32
    // d_in[1] = edge_index: unused by the reference, unused here.
    float* out = (float*)d_out;               // [8192, 1024] f32

    convert_x_kernel<<<(N_ROWS * DD / 4) / 256, 256>>>((const float4*)x);
    fused_kernel<<<NSM, 512>>>(out);
}

// round 15
// speedup vs baseline: 1.0852x; 1.0118x over previous
#include <cuda_runtime.h>
#include <cuda_fp16.h>
#include <stdint.h>
#include <stddef.h>

#define N_ROWS 8192
#define N_COLS 8192
#define DD     1024

#define NSM    148
#define KCHUNK 256
#define NKC    (N_COLS / KCHUNK)       // 32 k-chunks
#define NMB    (N_ROWS / 64)           // 128 m-bands (64 rows)
#define NUNITS (NMB * NKC)             // 4096, u = mb*32 + kc  (m-major!)
#define NTILES (NMB * (DD / 128))      // 1024, tile = mb*8 + nb

// Scratch (no cudaMalloc allowed)
static __device__ __half   g_E[(size_t)N_ROWS * N_COLS];    // exp(2m)*2^-4
static __device__ float    g_Spart[(size_t)N_ROWS * NKC];   // per-(row,kchunk) partials
static __device__ __half   g_Xh[(size_t)N_ROWS * DD];       // x fp16 [k][n]
static __device__ unsigned g_flag[NUNITS];                  // unit-ready flags

// ===========================================================================
// Threefry-2x32 (20 rounds), key = (0, 42); JAX partitionable combine o0^o1
// ===========================================================================
__device__ __forceinline__ uint32_t rotl32(uint32_t x, int d) {
    return __funnelshift_l(x, x, d);
}

__device__ __forceinline__ uint32_t threefry_bits(uint32_t t) {
    uint32_t x0 = 0u, x1 = t;
    const uint32_t ks1 = 42u, ks2 = 0x1BD11BF0u;
    x1 += ks1;
#define TF_R(r) { x0 += x1; x1 = rotl32(x1, (r)); x1 ^= x0; }
    TF_R(13) TF_R(15) TF_R(26) TF_R(6)
    x0 += ks1; x1 += ks2 + 1u;
    TF_R(17) TF_R(29) TF_R(16) TF_R(24)
    x0 += ks2; x1 += 2u;
    TF_R(13) TF_R(15) TF_R(26) TF_R(6)
    x1 += ks1 + 3u;
    TF_R(17) TF_R(29) TF_R(16) TF_R(24)
    x0 += ks1; x1 += ks2 + 4u;
    TF_R(13) TF_R(15) TF_R(26) TF_R(6)
    x0 += ks2; x1 += 5u;
#undef TF_R
    return x0 ^ x1;
}

// weight = exp(2*sqrt(2)*erfinv_xla(u)) * 2^-4 ; matches XLA's Giles poly
__device__ __forceinline__ float gibbs_weight(uint32_t bits) {
    float f = __uint_as_float((bits >> 9) | 0x3f800000u) - 1.0f;
    float u = f * 2.0f + -0.99999994f;
    u = fmaxf(u, -0.99999994f);

    float y = 1.0f - u * u;
    float l; asm("lg2.approx.ftz.f32 %0, %1;" : "=f"(l) : "f"(y));
    float w = l * -0.6931471805599453f;
    float p;
    if (w < 5.0f) {
        w -= 2.5f;
        p = 2.81022636e-08f;
        p = fmaf(p, w, 3.43273939e-07f);
        p = fmaf(p, w, -3.5233877e-06f);
        p = fmaf(p, w, -4.39150654e-06f);
        p = fmaf(p, w, 0.00021858087f);
        p = fmaf(p, w, -0.00125372503f);
        p = fmaf(p, w, -0.00417768164f);
        p = fmaf(p, w, 0.246640727f);
        p = fmaf(p, w, 1.50140941f);
    } else {
        w = sqrtf(w) - 3.0f;
        p = -0.000200214257f;
        p = fmaf(p, w, 0.000100950558f);
        p = fmaf(p, w, 0.00134934322f);
        p = fmaf(p, w, -0.00367342844f);
        p = fmaf(p, w, 0.00573950773f);
        p = fmaf(p, w, -0.0076224613f);
        p = fmaf(p, w, 0.00943887047f);
        p = fmaf(p, w, 1.00167406f);
        p = fmaf(p, w, 2.83297682f);
    }
    float t = p * u;
    float a = fmaf(t, 4.0805578f, -4.0f);       // 2^(t*2*sqrt2/ln2 - 4)
    float e; asm("ex2.approx.ftz.f32 %0, %1;" : "=f"(e) : "f"(a));
    return e;
}

// ===========================================================================
// Pass 0: x f32 -> fp16 + zero flags
// ===========================================================================
__global__ void convert_x_kernel(const float4* __restrict__ x) {
    int idx = blockIdx.x * 256 + threadIdx.x;
    if (idx < NUNITS) g_flag[idx] = 0u;
    float4 v = x[idx];
    __half2 h0 = __floats2half2_rn(v.x, v.y);
    __half2 h1 = __floats2half2_rn(v.z, v.w);
    *(uint2*)(g_Xh + (size_t)idx * 4) = make_uint2(*(uint32_t*)&h0, *(uint32_t*)&h1);
}

// ===========================================================================
// Fused: 148 CTAs x 512 thr.
// Warps 0-7  = PRODUCER (low wid -> LOW arbiter priority, fills slack)
// Warps 8-15 = CONSUMER GEMM (high wid -> wins issue arbitration; the HMMA
//              stream paces the SM).  [B300: arbiter is highest-wid-first]
// ===========================================================================
#define BM 64
#define BN 128
#define BK 32
#define SA_LD 40
#define SB_LD 136

__device__ __forceinline__ void cp_async16(void* smem, const void* gmem) {
    uint32_t s = (uint32_t)__cvta_generic_to_shared(smem);
    asm volatile("cp.async.cg.shared.global [%0], [%1], 16;\n" :: "r"(s), "l"(gmem));
}

__device__ __forceinline__ void wait_flag(int u) {
    unsigned v;
    for (;;) {
        asm volatile("ld.acquire.gpu.global.u32 %0, [%1];"
                     : "=r"(v) : "l"(g_flag + u) : "memory");
        if (v) break;
        __nanosleep(64);
    }
}

#define BAR_P() asm volatile("bar.sync 1, 256;" ::: "memory")   // producer warps
#define BAR_C() asm volatile("bar.sync 2, 256;" ::: "memory")   // consumer warps

__global__ __launch_bounds__(512, 1)
void fused_kernel(float* __restrict__ out) {
    __shared__ __half sA[2][BM][SA_LD];
    __shared__ __half sB[2][BK][SB_LD];
    __shared__ float  srow[BM];

    const int bid  = blockIdx.x;
    const int tid  = threadIdx.x;
    const int wid  = tid >> 5;
    const int lane = tid & 31;

    if (wid < 8) {
        // ================= producer: warps 0..7 (low priority) =============
        const int pw = wid;
        for (int u = bid; u < NUNITS; u += NSM) {
            const int mb = u >> 5, kc = u & 31;
#pragma unroll 1
            for (int rr = 0; rr < 8; rr++) {
                const int row = mb * 64 + pw * 8 + rr;
                const uint32_t base = (uint32_t)row * (uint32_t)N_COLS
                                    + (uint32_t)(kc * KCHUNK);
                float part = 0.0f;
#pragma unroll
                for (int j = 0; j < 4; j++) {
                    uint32_t c = (uint32_t)(lane * 2 + j * 64);
                    uint32_t t = base + c;
                    float e0 = gibbs_weight(threefry_bits(t));
                    float e1 = gibbs_weight(threefry_bits(t + 1u));
                    part += e0 + e1;
                    *(__half2*)(g_E + (size_t)base + c) = __floats2half2_rn(e0, e1);
                }
#pragma unroll
                for (int o = 16; o > 0; o >>= 1)
                    part += __shfl_xor_sync(0xffffffffu, part, o);
                if (lane == 0) g_Spart[row * NKC + kc] = part;
            }
            BAR_P();
            if (tid == 0) {
                __threadfence();
                asm volatile("st.release.gpu.global.u32 [%0], %1;"
                             :: "l"(g_flag + u), "r"(1u) : "memory");
            }
        }
        return;
    }

    // ================= consumer GEMM: warps 8..15 (high priority) ==========
    const int ct   = tid - 256;        // 0..255
    const int cwid = wid - 8;          // 0..7
    const int wm = cwid & 1;           // 2 warp-rows of 32
    const int wn = cwid >> 1;          // 4 warp-cols of 32
    const int aR = ct >> 2, aC = (ct & 3) * 8;
    const int bR = ct >> 4, bC = (ct & 15) * 8;

    for (int tile = bid; tile < NTILES; tile += NSM) {
        const int mb  = tile >> 3;
        const int bm0 = mb * BM;
        const int bn0 = (tile & 7) * BN;

        float acc[2][4][4];
#pragma unroll
        for (int a = 0; a < 2; a++)
#pragma unroll
            for (int b = 0; b < 4; b++)
#pragma unroll
                for (int c = 0; c < 4; c++) acc[a][b][c] = 0.0f;

#define LOAD_TILES(st, k0)                                                               \
    {                                                                                    \
        cp_async16(&sA[st][aR][aC],     g_E + (size_t)(bm0 + aR) * N_COLS + (k0) + aC);  \
        cp_async16(&sB[st][bR][bC],      g_Xh + (size_t)((k0) + bR) * DD + bn0 + bC);    \
        cp_async16(&sB[st][bR + 16][bC], g_Xh + (size_t)((k0) + bR + 16) * DD + bn0 + bC); \
        asm volatile("cp.async.commit_group;\n");                                        \
    }

        if (ct == 0) wait_flag(mb * NKC);
        BAR_C();
        LOAD_TILES(0, 0)

        const int KT = N_COLS / BK;  // 256
        for (int kt = 0; kt < KT; kt++) {
            const int st = kt & 1;
            if (kt + 1 < KT) {
                const int k0 = (kt + 1) * BK;
                if ((k0 & (KCHUNK - 1)) == 0) {
                    if (ct == 0) wait_flag(mb * NKC + (k0 >> 8));
                    BAR_C();
                }
                LOAD_TILES(st ^ 1, k0)
                asm volatile("cp.async.wait_group 1;\n");
            } else {
                asm volatile("cp.async.wait_group 0;\n");
            }
            BAR_C();

#pragma unroll
            for (int kk = 0; kk < 2; kk++) {
                uint32_t a[2][4];
#pragma unroll
                for (int mt = 0; mt < 2; mt++) {
                    uint32_t ad = (uint32_t)__cvta_generic_to_shared(
                        &sA[st][wm * 32 + mt * 16 + (lane & 15)][kk * 16 + (lane >> 4) * 8]);
                    asm volatile(
                        "ldmatrix.sync.aligned.m8n8.x4.shared.b16 {%0,%1,%2,%3}, [%4];"
                        : "=r"(a[mt][0]), "=r"(a[mt][1]), "=r"(a[mt][2]), "=r"(a[mt][3])
                        : "r"(ad));
                }
#pragma unroll
                for (int nt = 0; nt < 2; nt++) {
                    uint32_t b0, b1, b2, b3;
                    uint32_t bd = (uint32_t)__cvta_generic_to_shared(
                        &sB[st][kk * 16 + (lane & 15)][wn * 32 + nt * 16 + (lane >> 4) * 8]);
                    asm volatile(
                        "ldmatrix.sync.aligned.m8n8.x4.trans.shared.b16 {%0,%1,%2,%3}, [%4];"
                        : "=r"(b0), "=r"(b1), "=r"(b2), "=r"(b3)
                        : "r"(bd));
#pragma unroll
                    for (int mt = 0; mt < 2; mt++) {
                        asm volatile(
                            "mma.sync.aligned.m16n8k16.row.col.f32.f16.f16.f32 "
                            "{%0,%1,%2,%3}, {%4,%5,%6,%7}, {%8,%9}, {%0,%1,%2,%3};"
                            : "+f"(acc[mt][2 * nt][0]), "+f"(acc[mt][2 * nt][1]),
                              "+f"(acc[mt][2 * nt][2]), "+f"(acc[mt][2 * nt][3])
                            : "r"(a[mt][0]), "r"(a[mt][1]), "r"(a[mt][2]), "r"(a[mt][3]),
                              "r"(b0), "r"(b1));
                        asm volatile(
                            "mma.sync.aligned.m16n8k16.row.col.f32.f16.f16.f32 "
                            "{%0,%1,%2,%3}, {%4,%5,%6,%7}, {%8,%9}, {%0,%1,%2,%3};"
                            : "+f"(acc[mt][2 * nt + 1][0]), "+f"(acc[mt][2 * nt + 1][1]),
                              "+f"(acc[mt][2 * nt + 1][2]), "+f"(acc[mt][2 * nt + 1][3])
                            : "r"(a[mt][0]), "r"(a[mt][1]), "r"(a[mt][2]), "r"(a[mt][3]),
                              "r"(b2), "r"(b3));
                    }
                }
            }
            BAR_C();
        }
#undef LOAD_TILES

        // row scales: deterministic sum of 32 chunk partials (all flags acquired)
        {
            const int row = ct >> 2;
            float s = 0.0f;
#pragma unroll
            for (int k = 0; k < 8; k++)
                s += g_Spart[(bm0 + row) * NKC + (ct & 3) * 8 + k];
            s += __shfl_xor_sync(0xffffffffu, s, 1);
            s += __shfl_xor_sync(0xffffffffu, s, 2);
            if ((lane & 3) == 0) srow[row] = s;
        }
        BAR_C();

#pragma unroll
        for (int mt = 0; mt < 2; mt++) {
            const int lr = wm * 32 + mt * 16 + (lane >> 2);
            const int r0 = bm0 + lr;
            const float sc0 = 1.0f / srow[lr];
            const float sc1 = 1.0f / srow[lr + 8];
#pragma unroll
            for (int nt = 0; nt < 2; nt++)
#pragma unroll
                for (int h = 0; h < 2; h++) {
                    const int q  = nt * 2 + h;
                    const int c0 = bn0 + wn * 32 + nt * 16 + h * 8 + (lane & 3) * 2;
                    float2 v0 = make_float2(acc[mt][q][0] * sc0, acc[mt][q][1] * sc0);
                    float2 v1 = make_float2(acc[mt][q][2] * sc1, acc[mt][q][3] * sc1);
                    *(float2*)(out + (size_t)r0 * DD + c0)       = v0;
                    *(float2*)(out + (size_t)(r0 + 8) * DD + c0) = v1;
                }
        }
        BAR_C();
    }
}

// ---------------------------------------------------------------------------
extern "C" void kernel_launch(void* const* d_in, const int* in_sizes, int n_in,
                              void* d_out, int out_size) {
    (void)in_sizes; (void)n_in; (void)out_size;
    const float* x = (const float*)d_in[0];   // [8192, 1024] f32
    // d_in[1] = edge_index: unused by the reference, unused here.
    float* out = (float*)d_out;               // [8192, 1024] f32

    convert_x_kernel<<<(N_ROWS * DD / 4) / 256, 256>>>((const float4*)x);
    fused_kernel<<<NSM, 512>>>(out);
}